// round 12
// baseline (speedup 1.0000x reference)
#include <cuda_runtime.h>
#include <math_constants.h>
#include <cstdint>

// FCOS decode — R8 skeleton (warp-decoupled 2-stage cp.async.cg ring carrying
// cls + bbox + center) + work-stealing tail: 5 static tile-rounds per warp,
// remaining 3168 tiles grabbed from a global atomic counter.
//   inputs  : bbox [16,128,128,4] f32, center [16,128,128,1] f32, cls [16,128,128,80] f32
//   outputs : xywh [16,16384,4] f32 ++ cls_idx [16,16384] (as f32) ++ conf [16,16384] f32

#define N_LOC      (16 * 128 * 128)   // 262144
#define N_CLS      80
#define XYWH_ELEMS (N_LOC * 4)

#define THREADS        128
#define WARPS          (THREADS / 32)            // 4
#define WTILE          8                         // locations per stage
#define F4_PER_ROW     (N_CLS / 4)               // 20
#define F4_CLS         (WTILE * F4_PER_ROW)      // 160
#define BBOX_OFF       F4_CLS                    // f4 index 160
#define CTR_OFF        (F4_CLS + WTILE)          // f4 index 168
#define STAGE_F4       (F4_CLS + WTILE + 2)      // 170 f4 = 2720 B
#define N_WTILES       (N_LOC / WTILE)           // 32768

#define NUM_SMS        148
#define BLOCKS_PER_SM  10
#define GRID           (NUM_SMS * BLOCKS_PER_SM) // 1480
#define W_TOTAL        (GRID * WARPS)            // 5920
#define STATIC_ROUNDS  5
#define DYN_START      (STATIC_ROUNDS * W_TOTAL) // 29600 (dynamic pool: 3168 tiles)

__device__ int g_tile_ctr;

__global__ void fcos_init_ctr() { g_tile_ctr = DYN_START; }

__device__ __forceinline__ float4 fmax4(float4 a, float4 b) {
    float4 r;
    r.x = fmaxf(a.x, b.x); r.y = fmaxf(a.y, b.y);
    r.z = fmaxf(a.z, b.z); r.w = fmaxf(a.w, b.w);
    return r;
}
__device__ __forceinline__ void cp_cg16(void* smem_dst, const void* gsrc) {
    unsigned d = (unsigned)__cvta_generic_to_shared(smem_dst);
    asm volatile("cp.async.cg.shared.global [%0], [%1], 16;"
                 :: "r"(d), "l"(gsrc) : "memory");
}
__device__ __forceinline__ void cp_commit() {
    asm volatile("cp.async.commit_group;" ::: "memory");
}
__device__ __forceinline__ void cp_wait1() {
    asm volatile("cp.async.wait_group 1;" ::: "memory");
}

__global__ __launch_bounds__(THREADS, BLOCKS_PER_SM)
void fcos_decode_kernel(const float4* __restrict__ cls4,
                        const float4* __restrict__ bbox4,
                        const float4* __restrict__ ctr4,
                        float* __restrict__ out)
{
    __shared__ float4 sm[WARPS][2][STAGE_F4];    // 21.25 KB

    const int lane = threadIdx.x & 31;
    const int wid  = threadIdx.x >> 5;
    const int wgid = blockIdx.x * WARPS + wid;   // global warp id (0..5919)
    const int row  = lane >> 2;   // 0..7 (location within tile)
    const int part = lane & 3;    // 0..3 (20-class segment)

    float4 (*buf)[STAGE_F4] = sm[wid];

    // issue one tile's worth of cp.async (cls + bbox + center) into slot s
    auto issue_tile = [&](int s, int tile) {
        const float4* csrc = cls4 + (size_t)tile * F4_CLS;
        #pragma unroll
        for (int i = 0; i < 5; ++i)
            cp_cg16(&buf[s][lane + 32 * i], &csrc[lane + 32 * i]);
        if (lane < WTILE)
            cp_cg16(&buf[s][BBOX_OFF + lane], &bbox4[(size_t)tile * WTILE + lane]);
        if (lane < 2)
            cp_cg16(&buf[s][CTR_OFF + lane], &ctr4[(size_t)tile * 2 + lane]);
    };

    // next tile id: static rounds 1..4, then atomic grabs (-1 = exhausted)
    int round_next = 1;
    auto next_tile = [&]() -> int {
        int t = 0;
        if (lane == 0) {
            if (round_next < STATIC_ROUNDS) {
                t = wgid + round_next * W_TOTAL;
            } else {
                t = atomicAdd(&g_tile_ctr, 1);
                if (t >= N_WTILES) t = -1;
            }
        }
        ++round_next;
        return __shfl_sync(0xffffffffu, t, 0);
    };

    // ---- prologue ----
    int cur = wgid;                 // round 0, always valid (W_TOTAL < N_WTILES)
    issue_tile(0, cur);
    cp_commit();
    int nxt = next_tile();

    int bi = 0;
    while (cur >= 0) {
        // ---- issue next iteration's tile into the other buffer ----
        if (nxt >= 0) issue_tile(bi ^ 1, nxt);
        cp_commit();

        // ---- fetch the FOLLOWING tile id now (atomic latency hides under consume) ----
        int fut = (nxt >= 0) ? next_tile() : -1;

        cp_wait1();     // current tile's group complete (next still in flight)
        __syncwarp();   // cross-lane smem visibility

        // ---- load my 20 classes ----
        const float4* my = &buf[bi][row * F4_PER_ROW + part * 5];
        float4 v0 = my[0], v1 = my[1], v2 = my[2], v3 = my[3], v4 = my[4];

        // ---- max via shallow FMNMX tree (sigmoid monotonic -> raw logits) ----
        float4 a = fmax4(fmax4(v0, v1), fmax4(v2, v3));
        a = fmax4(a, v4);
        float best = fmaxf(fmaxf(a.x, a.y), fmaxf(a.z, a.w));

        // ---- first index equal to max: independent compares + min tree ----
        const int b0 = part * 20;
        int c0 = (v0.x == best) ? b0 + 0  : 1023;
        int c1 = (v0.y == best) ? b0 + 1  : 1023;
        int c2 = (v0.z == best) ? b0 + 2  : 1023;
        int c3 = (v0.w == best) ? b0 + 3  : 1023;
        int c4 = (v1.x == best) ? b0 + 4  : 1023;
        int c5 = (v1.y == best) ? b0 + 5  : 1023;
        int c6 = (v1.z == best) ? b0 + 6  : 1023;
        int c7 = (v1.w == best) ? b0 + 7  : 1023;
        int c8 = (v2.x == best) ? b0 + 8  : 1023;
        int c9 = (v2.y == best) ? b0 + 9  : 1023;
        int ca = (v2.z == best) ? b0 + 10 : 1023;
        int cb = (v2.w == best) ? b0 + 11 : 1023;
        int cc = (v3.x == best) ? b0 + 12 : 1023;
        int cd = (v3.y == best) ? b0 + 13 : 1023;
        int ce = (v3.z == best) ? b0 + 14 : 1023;
        int cf = (v3.w == best) ? b0 + 15 : 1023;
        int cg = (v4.x == best) ? b0 + 16 : 1023;
        int ch = (v4.y == best) ? b0 + 17 : 1023;
        int ci = (v4.z == best) ? b0 + 18 : 1023;
        int cj = (v4.w == best) ? b0 + 19 : 1023;
        int bidx = min(min(min(min(c0, c1), min(c2, c3)),
                           min(min(c4, c5), min(c6, c7))),
                       min(min(min(c8, c9), min(ca, cb)),
                           min(min(cc, cd), min(ce, cf))));
        bidx = min(bidx, min(min(cg, ch), min(ci, cj)));

        // ---- combine 4 segment-partials (tie -> lowest class index) ----
        #pragma unroll
        for (int off = 1; off <= 2; off <<= 1) {
            float ob = __shfl_xor_sync(0xffffffffu, best, off);
            int   oi = __shfl_xor_sync(0xffffffffu, bidx, off);
            if (ob > best || (ob == best && oi < bidx)) { best = ob; bidx = oi; }
        }

        // ---- owner lane: bbox decode + confidence + writes (all inputs in smem) ----
        if (part == 0) {
            int loc = cur * WTILE + row;

            float4 bb = buf[bi][BBOX_OFF + row];
            float l  = __expf(bb.x) * 8.0f;
            float tt = __expf(bb.y) * 8.0f;
            float r  = __expf(bb.z) * 8.0f;
            float bo = __expf(bb.w) * 8.0f;

            int h = (loc >> 7) & 127;
            int w =  loc       & 127;

            float4 xywh;
            xywh.x = ((float)w * 8.0f + 4.0f) - (l  - r ) * 0.5f;
            xywh.y = ((float)h * 8.0f + 4.0f) - (tt - bo) * 0.5f;
            xywh.z = l  + r;
            xywh.w = tt + bo;

            float ctr = reinterpret_cast<const float*>(&buf[bi][CTR_OFF])[row];
            // conf = sqrt(sigmoid(ctr)*sigmoid(best)) = rsqrt((1+e^-ctr)(1+e^-best))
            float ea = __expf(-ctr);
            float eb = __expf(-best);
            float conf = rsqrtf((1.0f + ea) * (1.0f + eb));

            __stcs(&reinterpret_cast<float4*>(out)[loc], xywh);
            __stcs(&out[XYWH_ELEMS + loc], (float)bidx);
            __stcs(&out[XYWH_ELEMS + N_LOC + loc], conf);
        }

        __syncwarp();   // lanes done reading buf[bi] before it is refilled
        cur = nxt;
        nxt = fut;
        bi ^= 1;
    }
}

extern "C" void kernel_launch(void* const* d_in, const int* in_sizes, int n_in,
                              void* d_out, int out_size)
{
    const float* bbox   = (const float*)d_in[0];
    const float* center = (const float*)d_in[1];
    const float* cls    = (const float*)d_in[2];
    float* out = (float*)d_out;

    fcos_init_ctr<<<1, 1>>>();
    fcos_decode_kernel<<<GRID, THREADS>>>(
        reinterpret_cast<const float4*>(cls),
        reinterpret_cast<const float4*>(bbox),
        reinterpret_cast<const float4*>(center),
        out);
}

// round 13
// speedup vs baseline: 1.1355x; 1.1355x over previous
#include <cuda_runtime.h>
#include <math_constants.h>
#include <cstdint>

// FCOS decode — R8 skeleton (warp-decoupled 2-stage cp.async.cg ring for cls),
// with bbox/center software-pipelined in registers (predicated LDG, one
// iteration of look-ahead) instead of riding the smem ring.
//   inputs  : bbox [16,128,128,4] f32, center [16,128,128,1] f32, cls [16,128,128,80] f32
//   outputs : xywh [16,16384,4] f32 ++ cls_idx [16,16384] (as f32) ++ conf [16,16384] f32

#define N_LOC      (16 * 128 * 128)   // 262144
#define N_CLS      80
#define XYWH_ELEMS (N_LOC * 4)

#define THREADS        128
#define WARPS          (THREADS / 32)            // 4
#define WTILE          8                         // locations per stage
#define F4_PER_ROW     (N_CLS / 4)               // 20
#define F4_CLS         (WTILE * F4_PER_ROW)      // 160 f4 = 2560 B
#define N_WTILES       (N_LOC / WTILE)           // 32768

#define NUM_SMS        148
#define BLOCKS_PER_SM  10
#define GRID           (NUM_SMS * BLOCKS_PER_SM) // 1480
#define W_TOTAL        (GRID * WARPS)            // 5920

__device__ __forceinline__ float4 fmax4(float4 a, float4 b) {
    float4 r;
    r.x = fmaxf(a.x, b.x); r.y = fmaxf(a.y, b.y);
    r.z = fmaxf(a.z, b.z); r.w = fmaxf(a.w, b.w);
    return r;
}
__device__ __forceinline__ void cp_cg16(void* smem_dst, const void* gsrc) {
    unsigned d = (unsigned)__cvta_generic_to_shared(smem_dst);
    asm volatile("cp.async.cg.shared.global [%0], [%1], 16;"
                 :: "r"(d), "l"(gsrc) : "memory");
}
__device__ __forceinline__ void cp_commit() {
    asm volatile("cp.async.commit_group;" ::: "memory");
}
__device__ __forceinline__ void cp_wait1() {
    asm volatile("cp.async.wait_group 1;" ::: "memory");
}

__global__ __launch_bounds__(THREADS, BLOCKS_PER_SM)
void fcos_decode_kernel(const float4* __restrict__ cls4,
                        const float4* __restrict__ bbox4,
                        const float*  __restrict__ center,
                        float* __restrict__ out)
{
    __shared__ float4 sm[WARPS][2][F4_CLS];      // 20 KB

    const int lane = threadIdx.x & 31;
    const int wid  = threadIdx.x >> 5;
    const int wgid = blockIdx.x * WARPS + wid;   // global warp id (0..5919)
    const int row  = lane >> 2;   // 0..7 (location within tile)
    const int part = lane & 3;    // 0..3 (20-class segment)
    const bool owner = (part == 0);

    float4 (*buf)[F4_CLS] = sm[wid];

    // issue one cls tile's cp.async group into slot s (coalesced 512B x 5)
    auto issue_cls = [&](int s, int tile) {
        const float4* csrc = cls4 + (size_t)tile * F4_CLS;
        #pragma unroll
        for (int i = 0; i < 5; ++i)
            cp_cg16(&buf[s][lane + 32 * i], &csrc[lane + 32 * i]);
    };

    // ---- prologue: issue cls tile 0; fetch bbox/ctr for tile 0 into regs ----
    issue_cls(0, wgid);
    cp_commit();
    float4 bb  = make_float4(0.f, 0.f, 0.f, 0.f);
    float  ctr = 0.f;
    if (owner) {
        bb  = __ldg(&bbox4[(size_t)wgid * WTILE + row]);
        ctr = __ldg(&center[(size_t)wgid * WTILE + row]);
    }

    int bi = 0;
    for (int k = wgid; k < N_WTILES; k += W_TOTAL) {
        const int  kn       = k + W_TOTAL;
        const bool has_next = (kn < N_WTILES);

        // ---- issue next tile's cls into the other buffer ----
        if (has_next) issue_cls(bi ^ 1, kn);
        cp_commit();

        // ---- prefetch next tile's bbox/ctr into registers (consumed next iter) ----
        float4 bb_n;
        float  ctr_n;
        if (has_next && owner) {
            bb_n  = __ldg(&bbox4[(size_t)kn * WTILE + row]);
            ctr_n = __ldg(&center[(size_t)kn * WTILE + row]);
        }

        cp_wait1();     // current cls group complete (next still in flight)
        __syncwarp();   // cross-lane smem visibility

        // ---- load my 20 classes ----
        const float4* my = &buf[bi][row * F4_PER_ROW + part * 5];
        float4 v0 = my[0], v1 = my[1], v2 = my[2], v3 = my[3], v4 = my[4];

        // ---- max via shallow FMNMX tree (sigmoid monotonic -> raw logits) ----
        float4 a = fmax4(fmax4(v0, v1), fmax4(v2, v3));
        a = fmax4(a, v4);
        float best = fmaxf(fmaxf(a.x, a.y), fmaxf(a.z, a.w));

        // ---- first index equal to max: independent compares + min tree ----
        const int b0 = part * 20;
        int c0 = (v0.x == best) ? b0 + 0  : 1023;
        int c1 = (v0.y == best) ? b0 + 1  : 1023;
        int c2 = (v0.z == best) ? b0 + 2  : 1023;
        int c3 = (v0.w == best) ? b0 + 3  : 1023;
        int c4 = (v1.x == best) ? b0 + 4  : 1023;
        int c5 = (v1.y == best) ? b0 + 5  : 1023;
        int c6 = (v1.z == best) ? b0 + 6  : 1023;
        int c7 = (v1.w == best) ? b0 + 7  : 1023;
        int c8 = (v2.x == best) ? b0 + 8  : 1023;
        int c9 = (v2.y == best) ? b0 + 9  : 1023;
        int ca = (v2.z == best) ? b0 + 10 : 1023;
        int cb = (v2.w == best) ? b0 + 11 : 1023;
        int cc = (v3.x == best) ? b0 + 12 : 1023;
        int cd = (v3.y == best) ? b0 + 13 : 1023;
        int ce = (v3.z == best) ? b0 + 14 : 1023;
        int cf = (v3.w == best) ? b0 + 15 : 1023;
        int cg = (v4.x == best) ? b0 + 16 : 1023;
        int ch = (v4.y == best) ? b0 + 17 : 1023;
        int ci = (v4.z == best) ? b0 + 18 : 1023;
        int cj = (v4.w == best) ? b0 + 19 : 1023;
        int bidx = min(min(min(min(c0, c1), min(c2, c3)),
                           min(min(c4, c5), min(c6, c7))),
                       min(min(min(c8, c9), min(ca, cb)),
                           min(min(cc, cd), min(ce, cf))));
        bidx = min(bidx, min(min(cg, ch), min(ci, cj)));

        // ---- combine 4 segment-partials (tie -> lowest class index) ----
        #pragma unroll
        for (int off = 1; off <= 2; off <<= 1) {
            float ob = __shfl_xor_sync(0xffffffffu, best, off);
            int   oi = __shfl_xor_sync(0xffffffffu, bidx, off);
            if (ob > best || (ob == best && oi < bidx)) { best = ob; bidx = oi; }
        }

        // ---- owner lane: bbox decode + confidence + writes (bbox/ctr in regs) ----
        if (owner) {
            int loc = k * WTILE + row;

            float l  = __expf(bb.x) * 8.0f;
            float tt = __expf(bb.y) * 8.0f;
            float r  = __expf(bb.z) * 8.0f;
            float bo = __expf(bb.w) * 8.0f;

            int h = (loc >> 7) & 127;
            int w =  loc       & 127;

            float4 xywh;
            xywh.x = ((float)w * 8.0f + 4.0f) - (l  - r ) * 0.5f;
            xywh.y = ((float)h * 8.0f + 4.0f) - (tt - bo) * 0.5f;
            xywh.z = l  + r;
            xywh.w = tt + bo;

            // conf = sqrt(sigmoid(ctr)*sigmoid(best)) = rsqrt((1+e^-ctr)(1+e^-best))
            float ea = __expf(-ctr);
            float eb = __expf(-best);
            float conf = rsqrtf((1.0f + ea) * (1.0f + eb));

            __stcs(&reinterpret_cast<float4*>(out)[loc], xywh);
            __stcs(&out[XYWH_ELEMS + loc], (float)bidx);
            __stcs(&out[XYWH_ELEMS + N_LOC + loc], conf);
        }

        __syncwarp();   // lanes done reading buf[bi] before it is refilled
        if (has_next && owner) { bb = bb_n; ctr = ctr_n; }
        bi ^= 1;
    }
}

extern "C" void kernel_launch(void* const* d_in, const int* in_sizes, int n_in,
                              void* d_out, int out_size)
{
    const float* bbox   = (const float*)d_in[0];
    const float* center = (const float*)d_in[1];
    const float* cls    = (const float*)d_in[2];
    float* out = (float*)d_out;

    fcos_decode_kernel<<<GRID, THREADS>>>(
        reinterpret_cast<const float4*>(cls),
        reinterpret_cast<const float4*>(bbox),
        center, out);
}